// round 12
// baseline (speedup 1.0000x reference)
#include <cuda_runtime.h>
#include <cuda_bf16.h>
#include <cstdint>

// ContrastiveLoss (NT-Xent) N=4096 D=512 tau=0.1 — INT8 symmetric GEMM.
// sim is symmetric: compute only upper-triangular 128x128 tile pairs
// (2080 of 4096); each exp() feeds the row denominator and (off-diagonal)
// the column denominator. Positive pairs captured from the bj==bi+32 tiles.
//
//   1) normalize: q[i] = round(127 * x/max|x|) int8 (row norm cancels),
//      fscale[i] = (max|x_i| / (127*||x_i||)) / sqrt(tau)
//   2) sym main:  per tile-pair (bi<=bj): s32 = Q_bi . Q_bj^T via int8
//      mma.sync m16n8k32 (fragments b16-compatible: 2 int8 per b16 unit);
//      epilogue v = s32 * fs_i * fs_j  (== cos/tau), mask + expf row/col sums
//   3) reduce:    loss = -mean(posv - log(denom))  (single block)

#define TWO_N 8192
#define NROWS 4096
#define DB16  256       // 512 int8 = 256 b16 units per row
#define INV_SQRT_TAU 3.16227766016837933f

#define MT 128
#define KC 32           // b16 units per stage (= 64 int8)
#define SSTR 40         // padded smem row stride (b16 units)
#define NBLK 64
#define NPAIRS 2080     // 64*65/2

__device__ uint16_t g_zn[(size_t)TWO_N * DB16];   // int8x2 packed
__device__ float g_fs[TWO_N];                     // per-row dequant scale
__device__ float g_denom[TWO_N];
__device__ float g_posv[TWO_N];

// ---------------------------------------------------------------------------
// 2 rows per block (128 threads each), float4 loads.
__global__ void normalize_kernel(const float* __restrict__ x1,
                                 const float* __restrict__ x2) {
    const int slot = threadIdx.x >> 7;          // 0,1
    const int t    = threadIdx.x & 127;
    const int row  = blockIdx.x * 2 + slot;
    const float4* src = (const float4*)((row < NROWS)
                        ? (x1 + (size_t)row * 512)
                        : (x2 + (size_t)(row - NROWS) * 512));
    const float4 f = src[t];

    float ss = f.x * f.x + f.y * f.y + f.z * f.z + f.w * f.w;
    float mx = fmaxf(fmaxf(fabsf(f.x), fabsf(f.y)), fmaxf(fabsf(f.z), fabsf(f.w)));
    #pragma unroll
    for (int o = 16; o > 0; o >>= 1) {
        ss += __shfl_xor_sync(0xffffffffu, ss, o);
        mx = fmaxf(mx, __shfl_xor_sync(0xffffffffu, mx, o));
    }
    __shared__ float s_ss[2][4], s_mx[2][4];
    const int w = t >> 5;
    if ((t & 31) == 0) { s_ss[slot][w] = ss; s_mx[slot][w] = mx; }
    __syncthreads();
    float tss = s_ss[slot][0] + s_ss[slot][1] + s_ss[slot][2] + s_ss[slot][3];
    float tmx = fmaxf(fmaxf(s_mx[slot][0], s_mx[slot][1]),
                      fmaxf(s_mx[slot][2], s_mx[slot][3]));
    tmx = fmaxf(tmx, 1e-20f);

    const float qs = 127.0f / tmx;
    char4 q;
    q.x = (char)__float2int_rn(f.x * qs);
    q.y = (char)__float2int_rn(f.y * qs);
    q.z = (char)__float2int_rn(f.z * qs);
    q.w = (char)__float2int_rn(f.w * qs);
    ((int*)g_zn)[(size_t)row * 128 + t] = *(int*)&q;

    if (t == 0) {
        const float norm = fmaxf(sqrtf(tss), 1e-8f);
        g_fs[row] = (tmx / (127.0f * norm)) * INV_SQRT_TAU;
        g_denom[row] = 0.f;
    }
}

// ---------------------------------------------------------------------------
__device__ __forceinline__ void cp_async16(uint32_t saddr, const void* gaddr) {
    asm volatile("cp.async.cg.shared.global [%0], [%1], 16;\n"
                 :: "r"(saddr), "l"(gaddr));
}
__device__ __forceinline__ void cp_commit() {
    asm volatile("cp.async.commit_group;\n" ::: "memory");
}
__device__ __forceinline__ void cp_wait1() {
    asm volatile("cp.async.wait_group 1;\n" ::: "memory");
}
__device__ __forceinline__ void cp_wait0() {
    asm volatile("cp.async.wait_group 0;\n" ::: "memory");
}

__global__ __launch_bounds__(256, 2)
void simclr_sym_kernel() {
    __shared__ __align__(16) uint16_t sA[2][MT * SSTR];
    __shared__ __align__(16) uint16_t sB[2][MT * SSTR];
    __shared__ float s_rden[MT];
    __shared__ float s_cden[MT];
    __shared__ float s_sca[MT];
    __shared__ float s_scb[MT];

    // ---- decode linear pair index -> (bi, bj) with bi <= bj ----
    const int idx = blockIdx.x;
    int bi = (int)(64.5f - sqrtf(64.5f * 64.5f - 2.0f * (float)idx));
    if (bi < 0) bi = 0;
    if (bi > NBLK - 1) bi = NBLK - 1;
    while (bi * (129 - bi) / 2 > idx) bi--;
    while ((bi + 1) * (128 - bi) / 2 <= idx) bi++;
    const int bj = bi + (idx - bi * (129 - bi) / 2);
    const int r0 = bi * MT;
    const int c0 = bj * MT;
    const bool offdiag = (bi != bj);

    const int t    = threadIdx.x;
    const int lane = t & 31;
    const int warp = t >> 5;
    const int m_base = (warp >> 1) * 32;   // 4 warps along M
    const int n_base = (warp & 1) * 64;    // 2 warps along N

    if (t < MT) {
        s_rden[t] = 0.f; s_cden[t] = 0.f;
        s_sca[t] = g_fs[r0 + t];
        s_scb[t] = g_fs[c0 + t];
    }

    // ldmatrix per-lane addressing (b16 units)
    const int a_r  = lane & 15;
    const int a_c8 = (lane >> 4) << 3;
    const int b_r  = (lane & 7) + ((lane >> 4) << 3);
    const int b_c8 = ((lane >> 3) & 1) << 3;

    int acc[2][8][4];
    #pragma unroll
    for (int mi = 0; mi < 2; mi++)
        #pragma unroll
        for (int ni = 0; ni < 8; ni++)
            #pragma unroll
            for (int q = 0; q < 4; q++) acc[mi][ni][q] = 0;

    // ---- stage loader: per stage 128 rows x 32 b16 (64B) per matrix ----
    auto load_stage = [&](int k0, int buf) {
        #pragma unroll
        for (int rep = 0; rep < 2; rep++) {
            const int i2 = t + rep * 256;
            const int row = i2 >> 2, chk = i2 & 3;
            const uint16_t* ga = g_zn + (size_t)(r0 + row) * DB16 + k0 + chk * 8;
            cp_async16((uint32_t)__cvta_generic_to_shared(&sA[buf][row * SSTR + chk * 8]), ga);
        }
        #pragma unroll
        for (int rep = 0; rep < 2; rep++) {
            const int i2 = t + rep * 256;
            const int row = i2 >> 2, chk = i2 & 3;
            const uint16_t* gb = g_zn + (size_t)(c0 + row) * DB16 + k0 + chk * 8;
            cp_async16((uint32_t)__cvta_generic_to_shared(&sB[buf][row * SSTR + chk * 8]), gb);
        }
    };

    load_stage(0, 0);
    cp_commit();

    const int NKC = DB16 / KC;  // 8
    for (int kc = 0; kc < NKC; kc++) {
        if (kc + 1 < NKC) {
            load_stage((kc + 1) * KC, (kc + 1) & 1);
            cp_commit();
            cp_wait1();
        } else {
            cp_wait0();
        }
        __syncthreads();

        const uint16_t* Ab = sA[kc & 1];
        const uint16_t* Bb = sB[kc & 1];

        #pragma unroll
        for (int ks = 0; ks < KC; ks += 16) {
            uint32_t a[2][4];
            #pragma unroll
            for (int mi = 0; mi < 2; mi++) {
                uint32_t ad = (uint32_t)__cvta_generic_to_shared(
                    Ab + (m_base + mi * 16 + a_r) * SSTR + ks + a_c8);
                asm volatile(
                    "ldmatrix.sync.aligned.m8n8.x4.shared.b16 {%0,%1,%2,%3}, [%4];\n"
                    : "=r"(a[mi][0]), "=r"(a[mi][1]), "=r"(a[mi][2]), "=r"(a[mi][3])
                    : "r"(ad));
            }
            #pragma unroll
            for (int ng = 0; ng < 4; ng++) {
                uint32_t b0, b1, b2, b3;
                uint32_t bd = (uint32_t)__cvta_generic_to_shared(
                    Bb + (n_base + ng * 16 + b_r) * SSTR + ks + b_c8);
                asm volatile(
                    "ldmatrix.sync.aligned.m8n8.x4.shared.b16 {%0,%1,%2,%3}, [%4];\n"
                    : "=r"(b0), "=r"(b1), "=r"(b2), "=r"(b3) : "r"(bd));
                #pragma unroll
                for (int mi = 0; mi < 2; mi++) {
                    asm volatile(
                        "mma.sync.aligned.m16n8k32.row.col.s32.s8.s8.s32 "
                        "{%0,%1,%2,%3}, {%4,%5,%6,%7}, {%8,%9}, {%0,%1,%2,%3};\n"
                        : "+r"(acc[mi][2 * ng][0]), "+r"(acc[mi][2 * ng][1]),
                          "+r"(acc[mi][2 * ng][2]), "+r"(acc[mi][2 * ng][3])
                        : "r"(a[mi][0]), "r"(a[mi][1]), "r"(a[mi][2]), "r"(a[mi][3]),
                          "r"(b0), "r"(b1));
                    asm volatile(
                        "mma.sync.aligned.m16n8k32.row.col.s32.s8.s8.s32 "
                        "{%0,%1,%2,%3}, {%4,%5,%6,%7}, {%8,%9}, {%0,%1,%2,%3};\n"
                        : "+r"(acc[mi][2 * ng + 1][0]), "+r"(acc[mi][2 * ng + 1][1]),
                          "+r"(acc[mi][2 * ng + 1][2]), "+r"(acc[mi][2 * ng + 1][3])
                        : "r"(a[mi][0]), "r"(a[mi][1]), "r"(a[mi][2]), "r"(a[mi][3]),
                          "r"(b2), "r"(b3));
                }
            }
        }
        __syncthreads();
    }

    // ---- epilogue: dequant, mask, exp, row sums + (off-diag) col sums ----
    const int g = lane >> 2, tig = lane & 3;
    float cp[8][2];
    #pragma unroll
    for (int ni = 0; ni < 8; ni++) { cp[ni][0] = 0.f; cp[ni][1] = 0.f; }

    auto proc = [&](int row, int col, float v, float& rs, float& cq) {
        if (((col ^ row) & 4095) == 0) {
            if (col != row) {               // positive pair: capture, excluded
                g_posv[row] = v;
                g_posv[col] = v;
            }
        } else {
            const float e = __expf(v);
            rs += e;
            cq += e;
        }
    };

    #pragma unroll
    for (int mi = 0; mi < 2; mi++) {
        float rs0 = 0.f, rs1 = 0.f;
        const int lrA = m_base + mi * 16 + g;
        const int rA = r0 + lrA;
        const int rB = rA + 8;
        const float fiA = s_sca[lrA];
        const float fiB = s_sca[lrA + 8];
        #pragma unroll
        for (int ni = 0; ni < 8; ni++) {
            const int lc = n_base + ni * 8 + tig * 2;
            const int cA = c0 + lc;
            const float fj0 = s_scb[lc], fj1 = s_scb[lc + 1];
            proc(rA, cA,     (float)acc[mi][ni][0] * fiA * fj0, rs0, cp[ni][0]);
            proc(rA, cA + 1, (float)acc[mi][ni][1] * fiA * fj1, rs0, cp[ni][1]);
            proc(rB, cA,     (float)acc[mi][ni][2] * fiB * fj0, rs1, cp[ni][0]);
            proc(rB, cA + 1, (float)acc[mi][ni][3] * fiB * fj1, rs1, cp[ni][1]);
        }
        rs0 += __shfl_xor_sync(0xffffffffu, rs0, 1);
        rs0 += __shfl_xor_sync(0xffffffffu, rs0, 2);
        rs1 += __shfl_xor_sync(0xffffffffu, rs1, 1);
        rs1 += __shfl_xor_sync(0xffffffffu, rs1, 2);
        if (tig == 0) {
            atomicAdd(&s_rden[lrA],     rs0);
            atomicAdd(&s_rden[lrA + 8], rs1);
        }
    }

    if (offdiag) {
        // column sums: butterfly over the g bits (lane bits 2..4)
        #pragma unroll
        for (int ni = 0; ni < 8; ni++) {
            #pragma unroll
            for (int qc = 0; qc < 2; qc++) {
                float s = cp[ni][qc];
                s += __shfl_xor_sync(0xffffffffu, s, 4);
                s += __shfl_xor_sync(0xffffffffu, s, 8);
                s += __shfl_xor_sync(0xffffffffu, s, 16);
                if (g == 0)
                    atomicAdd(&s_cden[n_base + ni * 8 + tig * 2 + qc], s);
            }
        }
    }

    __syncthreads();
    if (t < MT) {
        atomicAdd(&g_denom[r0 + t], s_rden[t]);
        if (offdiag) atomicAdd(&g_denom[c0 + t], s_cden[t]);
    }
}

// ---------------------------------------------------------------------------
__global__ void reduce_kernel(float* __restrict__ out) {
    const int t = threadIdx.x;          // 1024 threads, single block
    float v = 0.f;
    #pragma unroll
    for (int r = 0; r < 8; r++) {
        const int i = t + r * 1024;
        v += g_posv[i] - __logf(g_denom[i]);
    }
    #pragma unroll
    for (int o = 16; o > 0; o >>= 1) v += __shfl_xor_sync(0xffffffffu, v, o);
    __shared__ float sr[32];
    if ((t & 31) == 0) sr[t >> 5] = v;
    __syncthreads();
    if (t == 0) {
        float s = 0.f;
        #pragma unroll
        for (int i = 0; i < 32; i++) s += sr[i];
        out[0] = -s * (1.0f / (float)TWO_N);
    }
}

// ---------------------------------------------------------------------------
extern "C" void kernel_launch(void* const* d_in, const int* in_sizes, int n_in,
                              void* d_out, int out_size) {
    const float* x1 = (const float*)d_in[0];
    const float* x2 = (const float*)d_in[1];
    float* out = (float*)d_out;

    normalize_kernel<<<TWO_N / 2, 256>>>(x1, x2);
    simclr_sym_kernel<<<NPAIRS, 256>>>();
    reduce_kernel<<<1, 1024>>>(out);
}

// round 13
// speedup vs baseline: 1.6870x; 1.6870x over previous
#include <cuda_runtime.h>
#include <cuda_bf16.h>
#include <cstdint>

// ContrastiveLoss (NT-Xent) N=4096 D=512 tau=0.1 — FP8(e4m3) symmetric GEMM.
// sim is symmetric: compute only upper-triangular 128x128 tile pairs
// (2080 of 4096); each exp() feeds the row denominator and (off-diagonal)
// the column denominator. Positive pairs captured from the bj==bi+32 tiles.
//
// Measured sm_103a mma.sync rates: e4m3 k32 ~8cyc (fastest), s8 k32 ~16cyc,
// bf16 k16 ~4cyc -> fp8 is the best mma.sync format; tcgen05 unavailable
// (harness ptxas targets sm_103 non-a).
//
//   1) normalize: warp-per-row, zn = (1/sqrt(tau)) * x/||x|| -> fp8 e4m3
//   2) sym main:  per tile-pair (bi<=bj): C = A_bi . A_bj^T via fp8 mma.sync
//      m16n8k32 (fragments b16-compatible), fused mask + expf row/col sums
//   3) reduce:    loss = -mean(posv - log(denom))  (single block)

#define TWO_N 8192
#define NROWS 4096
#define DB16  256       // 512 fp8 = 256 b16 units per row
#define INV_SQRT_TAU 3.16227766016837933f

#define MT 128
#define KC 32           // b16 units per stage (= 64 fp8)
#define SSTR 40         // padded smem row stride (b16 units)
#define NBLK 64
#define NPAIRS 2080     // 64*65/2

__device__ uint16_t g_zn[(size_t)TWO_N * DB16];   // fp8x2 packed
__device__ float g_denom[TWO_N];
__device__ float g_posv[TWO_N];

// ---------------------------------------------------------------------------
// One warp per row: 4 float4 loads per lane (MLP=4), shfl-only reduction.
__global__ void normalize_kernel(const float* __restrict__ x1,
                                 const float* __restrict__ x2) {
    const int row  = blockIdx.x * 8 + (threadIdx.x >> 5);
    const int lane = threadIdx.x & 31;
    const float4* src = (const float4*)((row < NROWS)
                        ? (x1 + (size_t)row * 512)
                        : (x2 + (size_t)(row - NROWS) * 512));
    float4 f[4];
    #pragma unroll
    for (int i = 0; i < 4; i++) f[i] = src[lane + 32 * i];

    float ss = 0.f;
    #pragma unroll
    for (int i = 0; i < 4; i++)
        ss += f[i].x * f[i].x + f[i].y * f[i].y + f[i].z * f[i].z + f[i].w * f[i].w;
    #pragma unroll
    for (int o = 16; o > 0; o >>= 1) ss += __shfl_xor_sync(0xffffffffu, ss, o);

    const float scale = INV_SQRT_TAU / fmaxf(sqrtf(ss), 1e-8f);
    uint32_t* dst = (uint32_t*)g_zn + (size_t)row * 128;
    #pragma unroll
    for (int i = 0; i < 4; i++) {
        uint16_t lo, hi;
        asm("cvt.rn.satfinite.e4m3x2.f32 %0, %1, %2;"
            : "=h"(lo) : "f"(f[i].y * scale), "f"(f[i].x * scale));
        asm("cvt.rn.satfinite.e4m3x2.f32 %0, %1, %2;"
            : "=h"(hi) : "f"(f[i].w * scale), "f"(f[i].z * scale));
        dst[lane + 32 * i] = (uint32_t)lo | ((uint32_t)hi << 16);
    }
    if (lane == 0) g_denom[row] = 0.f;
}

// ---------------------------------------------------------------------------
__device__ __forceinline__ void cp_async16(uint32_t saddr, const void* gaddr) {
    asm volatile("cp.async.cg.shared.global [%0], [%1], 16;\n"
                 :: "r"(saddr), "l"(gaddr));
}
__device__ __forceinline__ void cp_commit() {
    asm volatile("cp.async.commit_group;\n" ::: "memory");
}
__device__ __forceinline__ void cp_wait1() {
    asm volatile("cp.async.wait_group 1;\n" ::: "memory");
}
__device__ __forceinline__ void cp_wait0() {
    asm volatile("cp.async.wait_group 0;\n" ::: "memory");
}

__global__ __launch_bounds__(256, 2)
void simclr_sym_kernel() {
    __shared__ __align__(16) uint16_t sA[2][MT * SSTR];
    __shared__ __align__(16) uint16_t sB[2][MT * SSTR];
    __shared__ float s_rden[MT];
    __shared__ float s_cden[MT];

    // ---- decode linear pair index -> (bi, bj) with bi <= bj ----
    const int idx = blockIdx.x;
    int bi = (int)(64.5f - sqrtf(64.5f * 64.5f - 2.0f * (float)idx));
    if (bi < 0) bi = 0;
    if (bi > NBLK - 1) bi = NBLK - 1;
    while (bi * (129 - bi) / 2 > idx) bi--;
    while ((bi + 1) * (128 - bi) / 2 <= idx) bi++;
    const int bj = bi + (idx - bi * (129 - bi) / 2);
    const int r0 = bi * MT;
    const int c0 = bj * MT;
    const bool offdiag = (bi != bj);

    const int t    = threadIdx.x;
    const int lane = t & 31;
    const int warp = t >> 5;
    const int m_base = (warp >> 1) * 32;   // 4 warps along M
    const int n_base = (warp & 1) * 64;    // 2 warps along N

    if (t < MT) { s_rden[t] = 0.f; s_cden[t] = 0.f; }

    // ldmatrix per-lane addressing (b16 units)
    const int a_r  = lane & 15;
    const int a_c8 = (lane >> 4) << 3;
    const int b_r  = (lane & 7) + ((lane >> 4) << 3);
    const int b_c8 = ((lane >> 3) & 1) << 3;

    float acc[2][8][4];
    #pragma unroll
    for (int mi = 0; mi < 2; mi++)
        #pragma unroll
        for (int ni = 0; ni < 8; ni++)
            #pragma unroll
            for (int q = 0; q < 4; q++) acc[mi][ni][q] = 0.f;

    // ---- stage loader: per stage 128 rows x 32 b16 (64B) per matrix ----
    auto load_stage = [&](int k0, int buf) {
        #pragma unroll
        for (int rep = 0; rep < 2; rep++) {
            const int i2 = t + rep * 256;
            const int row = i2 >> 2, chk = i2 & 3;
            const uint16_t* ga = g_zn + (size_t)(r0 + row) * DB16 + k0 + chk * 8;
            cp_async16((uint32_t)__cvta_generic_to_shared(&sA[buf][row * SSTR + chk * 8]), ga);
        }
        #pragma unroll
        for (int rep = 0; rep < 2; rep++) {
            const int i2 = t + rep * 256;
            const int row = i2 >> 2, chk = i2 & 3;
            const uint16_t* gb = g_zn + (size_t)(c0 + row) * DB16 + k0 + chk * 8;
            cp_async16((uint32_t)__cvta_generic_to_shared(&sB[buf][row * SSTR + chk * 8]), gb);
        }
    };

    load_stage(0, 0);
    cp_commit();

    const int NKC = DB16 / KC;  // 8
    for (int kc = 0; kc < NKC; kc++) {
        if (kc + 1 < NKC) {
            load_stage((kc + 1) * KC, (kc + 1) & 1);
            cp_commit();
            cp_wait1();
        } else {
            cp_wait0();
        }
        __syncthreads();

        const uint16_t* Ab = sA[kc & 1];
        const uint16_t* Bb = sB[kc & 1];

        #pragma unroll
        for (int ks = 0; ks < KC; ks += 16) {
            uint32_t a[2][4];
            #pragma unroll
            for (int mi = 0; mi < 2; mi++) {
                uint32_t ad = (uint32_t)__cvta_generic_to_shared(
                    Ab + (m_base + mi * 16 + a_r) * SSTR + ks + a_c8);
                asm volatile(
                    "ldmatrix.sync.aligned.m8n8.x4.shared.b16 {%0,%1,%2,%3}, [%4];\n"
                    : "=r"(a[mi][0]), "=r"(a[mi][1]), "=r"(a[mi][2]), "=r"(a[mi][3])
                    : "r"(ad));
            }
            #pragma unroll
            for (int ng = 0; ng < 4; ng++) {
                uint32_t b0, b1, b2, b3;
                uint32_t bd = (uint32_t)__cvta_generic_to_shared(
                    Bb + (n_base + ng * 16 + b_r) * SSTR + ks + b_c8);
                asm volatile(
                    "ldmatrix.sync.aligned.m8n8.x4.shared.b16 {%0,%1,%2,%3}, [%4];\n"
                    : "=r"(b0), "=r"(b1), "=r"(b2), "=r"(b3) : "r"(bd));
                #pragma unroll
                for (int mi = 0; mi < 2; mi++) {
                    asm volatile(
                        "mma.sync.aligned.m16n8k32.row.col.f32.e4m3.e4m3.f32 "
                        "{%0,%1,%2,%3}, {%4,%5,%6,%7}, {%8,%9}, {%0,%1,%2,%3};\n"
                        : "+f"(acc[mi][2 * ng][0]), "+f"(acc[mi][2 * ng][1]),
                          "+f"(acc[mi][2 * ng][2]), "+f"(acc[mi][2 * ng][3])
                        : "r"(a[mi][0]), "r"(a[mi][1]), "r"(a[mi][2]), "r"(a[mi][3]),
                          "r"(b0), "r"(b1));
                    asm volatile(
                        "mma.sync.aligned.m16n8k32.row.col.f32.e4m3.e4m3.f32 "
                        "{%0,%1,%2,%3}, {%4,%5,%6,%7}, {%8,%9}, {%0,%1,%2,%3};\n"
                        : "+f"(acc[mi][2 * ng + 1][0]), "+f"(acc[mi][2 * ng + 1][1]),
                          "+f"(acc[mi][2 * ng + 1][2]), "+f"(acc[mi][2 * ng + 1][3])
                        : "r"(a[mi][0]), "r"(a[mi][1]), "r"(a[mi][2]), "r"(a[mi][3]),
                          "r"(b2), "r"(b3));
                }
            }
        }
        __syncthreads();
    }

    // ---- epilogue: mask, exp, row sums + (off-diag) col sums ----
    const int g = lane >> 2, tig = lane & 3;
    float cp[8][2];
    #pragma unroll
    for (int ni = 0; ni < 8; ni++) { cp[ni][0] = 0.f; cp[ni][1] = 0.f; }

    auto proc = [&](int row, int col, float v, float& rs, float& cq) {
        if (((col ^ row) & 4095) == 0) {
            if (col != row) {               // positive pair: capture, excluded
                g_posv[row] = v;
                g_posv[col] = v;
            }
        } else {
            const float e = __expf(v);
            rs += e;
            cq += e;
        }
    };

    #pragma unroll
    for (int mi = 0; mi < 2; mi++) {
        float rs0 = 0.f, rs1 = 0.f;
        const int rA = r0 + m_base + mi * 16 + g;
        const int rB = rA + 8;
        #pragma unroll
        for (int ni = 0; ni < 8; ni++) {
            const int cA = c0 + n_base + ni * 8 + tig * 2;
            proc(rA, cA,     acc[mi][ni][0], rs0, cp[ni][0]);
            proc(rA, cA + 1, acc[mi][ni][1], rs0, cp[ni][1]);
            proc(rB, cA,     acc[mi][ni][2], rs1, cp[ni][0]);
            proc(rB, cA + 1, acc[mi][ni][3], rs1, cp[ni][1]);
        }
        rs0 += __shfl_xor_sync(0xffffffffu, rs0, 1);
        rs0 += __shfl_xor_sync(0xffffffffu, rs0, 2);
        rs1 += __shfl_xor_sync(0xffffffffu, rs1, 1);
        rs1 += __shfl_xor_sync(0xffffffffu, rs1, 2);
        if (tig == 0) {
            atomicAdd(&s_rden[m_base + mi * 16 + g],     rs0);
            atomicAdd(&s_rden[m_base + mi * 16 + g + 8], rs1);
        }
    }

    if (offdiag) {
        // column sums: butterfly over the g bits (lane bits 2..4)
        #pragma unroll
        for (int ni = 0; ni < 8; ni++) {
            #pragma unroll
            for (int qc = 0; qc < 2; qc++) {
                float s = cp[ni][qc];
                s += __shfl_xor_sync(0xffffffffu, s, 4);
                s += __shfl_xor_sync(0xffffffffu, s, 8);
                s += __shfl_xor_sync(0xffffffffu, s, 16);
                if (g == 0)
                    atomicAdd(&s_cden[n_base + ni * 8 + tig * 2 + qc], s);
            }
        }
    }

    __syncthreads();
    if (t < MT) {
        atomicAdd(&g_denom[r0 + t], s_rden[t]);
        if (offdiag) atomicAdd(&g_denom[c0 + t], s_cden[t]);
    }
}

// ---------------------------------------------------------------------------
__global__ void reduce_kernel(float* __restrict__ out) {
    const int t = threadIdx.x;          // 1024 threads, single block
    float v = 0.f;
    #pragma unroll
    for (int r = 0; r < 8; r++) {
        const int i = t + r * 1024;
        v += g_posv[i] - __logf(g_denom[i]);
    }
    #pragma unroll
    for (int o = 16; o > 0; o >>= 1) v += __shfl_xor_sync(0xffffffffu, v, o);
    __shared__ float sr[32];
    if ((t & 31) == 0) sr[t >> 5] = v;
    __syncthreads();
    if (t == 0) {
        float s = 0.f;
        #pragma unroll
        for (int i = 0; i < 32; i++) s += sr[i];
        out[0] = -s * (1.0f / (float)TWO_N);
    }
}

// ---------------------------------------------------------------------------
extern "C" void kernel_launch(void* const* d_in, const int* in_sizes, int n_in,
                              void* d_out, int out_size) {
    const float* x1 = (const float*)d_in[0];
    const float* x2 = (const float*)d_in[1];
    float* out = (float*)d_out;

    normalize_kernel<<<TWO_N / 8, 256>>>(x1, x2);
    simclr_sym_kernel<<<NPAIRS, 256>>>();
    reduce_kernel<<<1, 1024>>>(out);
}

// round 14
// speedup vs baseline: 1.7593x; 1.0429x over previous
#include <cuda_runtime.h>
#include <cuda_bf16.h>
#include <cstdint>

// ContrastiveLoss (NT-Xent) N=4096 D=512 tau=0.1 — FP8(e4m3) symmetric GEMM.
// sim is symmetric: compute only upper-triangular 128x128 tile pairs
// (2080 of 4096); each exp() feeds the row denominator and (off-diagonal)
// the column denominator. Positive pairs captured from the bj==bi+32 tiles.
// Final loss reduction fused into the last CTA (atomic counter).
//
// Measured sm_103a mma.sync: ~512 MACs/cyc/SM in bf16 AND e4m3 (int8 half);
// main kernel sits at that roofline. tcgen05 unavailable (ptxas targets
// sm_103 non-a in this harness).

#define TWO_N 8192
#define NROWS 4096
#define DB16  256       // 512 fp8 = 256 b16 units per row
#define INV_SQRT_TAU 3.16227766016837933f

#define MT 128
#define KC 32           // b16 units per stage (= 64 fp8)
#define SSTR 40         // padded smem row stride (b16 units)
#define NBLK 64
#define NPAIRS 2080     // 64*65/2

__device__ uint16_t g_zn[(size_t)TWO_N * DB16];   // fp8x2 packed
__device__ float g_denom[TWO_N];
__device__ float g_posv[TWO_N];
__device__ unsigned g_ctr;

// ---------------------------------------------------------------------------
// 2 rows per warp: 8 x 16B loads per lane (MLP=8), shfl-only reductions.
__global__ void normalize_kernel(const float* __restrict__ x1,
                                 const float* __restrict__ x2) {
    const int warp = threadIdx.x >> 5;            // 0..7
    const int lane = threadIdx.x & 31;
    const int row0 = blockIdx.x * 16 + warp * 2;  // 512 blocks
    const int row1 = row0 + 1;

    const float4* s0 = (const float4*)((row0 < NROWS)
                       ? (x1 + (size_t)row0 * 512)
                       : (x2 + (size_t)(row0 - NROWS) * 512));
    const float4* s1 = (const float4*)((row1 < NROWS)
                       ? (x1 + (size_t)row1 * 512)
                       : (x2 + (size_t)(row1 - NROWS) * 512));
    float4 f0[4], f1[4];
    #pragma unroll
    for (int i = 0; i < 4; i++) f0[i] = s0[lane + 32 * i];
    #pragma unroll
    for (int i = 0; i < 4; i++) f1[i] = s1[lane + 32 * i];

    float ss0 = 0.f, ss1 = 0.f;
    #pragma unroll
    for (int i = 0; i < 4; i++) {
        ss0 += f0[i].x * f0[i].x + f0[i].y * f0[i].y + f0[i].z * f0[i].z + f0[i].w * f0[i].w;
        ss1 += f1[i].x * f1[i].x + f1[i].y * f1[i].y + f1[i].z * f1[i].z + f1[i].w * f1[i].w;
    }
    #pragma unroll
    for (int o = 16; o > 0; o >>= 1) {
        ss0 += __shfl_xor_sync(0xffffffffu, ss0, o);
        ss1 += __shfl_xor_sync(0xffffffffu, ss1, o);
    }

    const float sc0 = INV_SQRT_TAU / fmaxf(sqrtf(ss0), 1e-8f);
    const float sc1 = INV_SQRT_TAU / fmaxf(sqrtf(ss1), 1e-8f);
    uint32_t* d0 = (uint32_t*)g_zn + (size_t)row0 * 128;
    uint32_t* d1 = (uint32_t*)g_zn + (size_t)row1 * 128;
    #pragma unroll
    for (int i = 0; i < 4; i++) {
        uint16_t lo, hi;
        asm("cvt.rn.satfinite.e4m3x2.f32 %0, %1, %2;"
            : "=h"(lo) : "f"(f0[i].y * sc0), "f"(f0[i].x * sc0));
        asm("cvt.rn.satfinite.e4m3x2.f32 %0, %1, %2;"
            : "=h"(hi) : "f"(f0[i].w * sc0), "f"(f0[i].z * sc0));
        d0[lane + 32 * i] = (uint32_t)lo | ((uint32_t)hi << 16);
        asm("cvt.rn.satfinite.e4m3x2.f32 %0, %1, %2;"
            : "=h"(lo) : "f"(f1[i].y * sc1), "f"(f1[i].x * sc1));
        asm("cvt.rn.satfinite.e4m3x2.f32 %0, %1, %2;"
            : "=h"(hi) : "f"(f1[i].w * sc1), "f"(f1[i].z * sc1));
        d1[lane + 32 * i] = (uint32_t)lo | ((uint32_t)hi << 16);
    }
    if (lane == 0) {
        g_denom[row0] = 0.f;
        g_denom[row1] = 0.f;
        if (row0 == 0) g_ctr = 0u;
    }
}

// ---------------------------------------------------------------------------
__device__ __forceinline__ void cp_async16(uint32_t saddr, const void* gaddr) {
    asm volatile("cp.async.cg.shared.global [%0], [%1], 16;\n"
                 :: "r"(saddr), "l"(gaddr));
}
__device__ __forceinline__ void cp_commit() {
    asm volatile("cp.async.commit_group;\n" ::: "memory");
}
__device__ __forceinline__ void cp_wait1() {
    asm volatile("cp.async.wait_group 1;\n" ::: "memory");
}
__device__ __forceinline__ void cp_wait0() {
    asm volatile("cp.async.wait_group 0;\n" ::: "memory");
}

__global__ __launch_bounds__(256, 2)
void simclr_sym_kernel(float* __restrict__ out) {
    __shared__ __align__(16) uint16_t sA[2][MT * SSTR];
    __shared__ __align__(16) uint16_t sB[2][MT * SSTR];
    __shared__ float s_rden[MT];
    __shared__ float s_cden[MT];

    // ---- decode linear pair index -> (bi, bj) with bi <= bj ----
    const int idx = blockIdx.x;
    int bi = (int)(64.5f - sqrtf(64.5f * 64.5f - 2.0f * (float)idx));
    if (bi < 0) bi = 0;
    if (bi > NBLK - 1) bi = NBLK - 1;
    while (bi * (129 - bi) / 2 > idx) bi--;
    while ((bi + 1) * (128 - bi) / 2 <= idx) bi++;
    const int bj = bi + (idx - bi * (129 - bi) / 2);
    const int r0 = bi * MT;
    const int c0 = bj * MT;
    const bool offdiag = (bi != bj);

    const int t    = threadIdx.x;
    const int lane = t & 31;
    const int warp = t >> 5;
    const int m_base = (warp >> 1) * 32;   // 4 warps along M
    const int n_base = (warp & 1) * 64;    // 2 warps along N

    if (t < MT) { s_rden[t] = 0.f; s_cden[t] = 0.f; }

    // ldmatrix per-lane addressing (b16 units)
    const int a_r  = lane & 15;
    const int a_c8 = (lane >> 4) << 3;
    const int b_r  = (lane & 7) + ((lane >> 4) << 3);
    const int b_c8 = ((lane >> 3) & 1) << 3;

    float acc[2][8][4];
    #pragma unroll
    for (int mi = 0; mi < 2; mi++)
        #pragma unroll
        for (int ni = 0; ni < 8; ni++)
            #pragma unroll
            for (int q = 0; q < 4; q++) acc[mi][ni][q] = 0.f;

    // ---- stage loader: per stage 128 rows x 32 b16 (64B) per matrix ----
    auto load_stage = [&](int k0, int buf) {
        #pragma unroll
        for (int rep = 0; rep < 2; rep++) {
            const int i2 = t + rep * 256;
            const int row = i2 >> 2, chk = i2 & 3;
            const uint16_t* ga = g_zn + (size_t)(r0 + row) * DB16 + k0 + chk * 8;
            cp_async16((uint32_t)__cvta_generic_to_shared(&sA[buf][row * SSTR + chk * 8]), ga);
        }
        #pragma unroll
        for (int rep = 0; rep < 2; rep++) {
            const int i2 = t + rep * 256;
            const int row = i2 >> 2, chk = i2 & 3;
            const uint16_t* gb = g_zn + (size_t)(c0 + row) * DB16 + k0 + chk * 8;
            cp_async16((uint32_t)__cvta_generic_to_shared(&sB[buf][row * SSTR + chk * 8]), gb);
        }
    };

    load_stage(0, 0);
    cp_commit();

    const int NKC = DB16 / KC;  // 8
    for (int kc = 0; kc < NKC; kc++) {
        if (kc + 1 < NKC) {
            load_stage((kc + 1) * KC, (kc + 1) & 1);
            cp_commit();
            cp_wait1();
        } else {
            cp_wait0();
        }
        __syncthreads();

        const uint16_t* Ab = sA[kc & 1];
        const uint16_t* Bb = sB[kc & 1];

        #pragma unroll
        for (int ks = 0; ks < KC; ks += 16) {
            uint32_t a[2][4];
            #pragma unroll
            for (int mi = 0; mi < 2; mi++) {
                uint32_t ad = (uint32_t)__cvta_generic_to_shared(
                    Ab + (m_base + mi * 16 + a_r) * SSTR + ks + a_c8);
                asm volatile(
                    "ldmatrix.sync.aligned.m8n8.x4.shared.b16 {%0,%1,%2,%3}, [%4];\n"
                    : "=r"(a[mi][0]), "=r"(a[mi][1]), "=r"(a[mi][2]), "=r"(a[mi][3])
                    : "r"(ad));
            }
            #pragma unroll
            for (int ng = 0; ng < 4; ng++) {
                uint32_t b0, b1, b2, b3;
                uint32_t bd = (uint32_t)__cvta_generic_to_shared(
                    Bb + (n_base + ng * 16 + b_r) * SSTR + ks + b_c8);
                asm volatile(
                    "ldmatrix.sync.aligned.m8n8.x4.shared.b16 {%0,%1,%2,%3}, [%4];\n"
                    : "=r"(b0), "=r"(b1), "=r"(b2), "=r"(b3) : "r"(bd));
                #pragma unroll
                for (int mi = 0; mi < 2; mi++) {
                    asm volatile(
                        "mma.sync.aligned.m16n8k32.row.col.f32.e4m3.e4m3.f32 "
                        "{%0,%1,%2,%3}, {%4,%5,%6,%7}, {%8,%9}, {%0,%1,%2,%3};\n"
                        : "+f"(acc[mi][2 * ng][0]), "+f"(acc[mi][2 * ng][1]),
                          "+f"(acc[mi][2 * ng][2]), "+f"(acc[mi][2 * ng][3])
                        : "r"(a[mi][0]), "r"(a[mi][1]), "r"(a[mi][2]), "r"(a[mi][3]),
                          "r"(b0), "r"(b1));
                    asm volatile(
                        "mma.sync.aligned.m16n8k32.row.col.f32.e4m3.e4m3.f32 "
                        "{%0,%1,%2,%3}, {%4,%5,%6,%7}, {%8,%9}, {%0,%1,%2,%3};\n"
                        : "+f"(acc[mi][2 * ng + 1][0]), "+f"(acc[mi][2 * ng + 1][1]),
                          "+f"(acc[mi][2 * ng + 1][2]), "+f"(acc[mi][2 * ng + 1][3])
                        : "r"(a[mi][0]), "r"(a[mi][1]), "r"(a[mi][2]), "r"(a[mi][3]),
                          "r"(b2), "r"(b3));
                }
            }
        }
        __syncthreads();
    }

    // ---- epilogue: mask, exp, row sums + (off-diag) col sums ----
    const int g = lane >> 2, tig = lane & 3;
    float cp[8][2];
    #pragma unroll
    for (int ni = 0; ni < 8; ni++) { cp[ni][0] = 0.f; cp[ni][1] = 0.f; }

    auto proc = [&](int row, int col, float v, float& rs, float& cq) {
        if (((col ^ row) & 4095) == 0) {
            if (col != row) {               // positive pair: capture, excluded
                g_posv[row] = v;
                g_posv[col] = v;
            }
        } else {
            const float e = __expf(v);
            rs += e;
            cq += e;
        }
    };

    #pragma unroll
    for (int mi = 0; mi < 2; mi++) {
        float rs0 = 0.f, rs1 = 0.f;
        const int rA = r0 + m_base + mi * 16 + g;
        const int rB = rA + 8;
        #pragma unroll
        for (int ni = 0; ni < 8; ni++) {
            const int cA = c0 + n_base + ni * 8 + tig * 2;
            proc(rA, cA,     acc[mi][ni][0], rs0, cp[ni][0]);
            proc(rA, cA + 1, acc[mi][ni][1], rs0, cp[ni][1]);
            proc(rB, cA,     acc[mi][ni][2], rs1, cp[ni][0]);
            proc(rB, cA + 1, acc[mi][ni][3], rs1, cp[ni][1]);
        }
        rs0 += __shfl_xor_sync(0xffffffffu, rs0, 1);
        rs0 += __shfl_xor_sync(0xffffffffu, rs0, 2);
        rs1 += __shfl_xor_sync(0xffffffffu, rs1, 1);
        rs1 += __shfl_xor_sync(0xffffffffu, rs1, 2);
        if (tig == 0) {
            atomicAdd(&s_rden[m_base + mi * 16 + g],     rs0);
            atomicAdd(&s_rden[m_base + mi * 16 + g + 8], rs1);
        }
    }

    if (offdiag) {
        // column sums: butterfly over the g bits (lane bits 2..4)
        #pragma unroll
        for (int ni = 0; ni < 8; ni++) {
            #pragma unroll
            for (int qc = 0; qc < 2; qc++) {
                float s = cp[ni][qc];
                s += __shfl_xor_sync(0xffffffffu, s, 4);
                s += __shfl_xor_sync(0xffffffffu, s, 8);
                s += __shfl_xor_sync(0xffffffffu, s, 16);
                if (g == 0)
                    atomicAdd(&s_cden[n_base + ni * 8 + tig * 2 + qc], s);
            }
        }
    }

    __syncthreads();
    if (t < MT) {
        atomicAdd(&g_denom[r0 + t], s_rden[t]);
        if (offdiag) atomicAdd(&g_denom[c0 + t], s_cden[t]);
    }

    // ---- fused final reduction: last CTA computes the loss ----
    __threadfence();
    __shared__ unsigned s_last;
    if (t == 0) s_last = (atomicAdd(&g_ctr, 1u) == NPAIRS - 1) ? 1u : 0u;
    __syncthreads();
    if (s_last) {
        float v = 0.f;
        #pragma unroll
        for (int r = 0; r < 32; r++) {
            const int i = t + r * 256;
            v += g_posv[i] - __logf(g_denom[i]);
        }
        #pragma unroll
        for (int o = 16; o > 0; o >>= 1) v += __shfl_xor_sync(0xffffffffu, v, o);
        __shared__ float sr[8];
        if ((t & 31) == 0) sr[t >> 5] = v;
        __syncthreads();
        if (t == 0) {
            float s = 0.f;
            #pragma unroll
            for (int i = 0; i < 8; i++) s += sr[i];
            out[0] = -s * (1.0f / (float)TWO_N);
        }
    }
}

// ---------------------------------------------------------------------------
extern "C" void kernel_launch(void* const* d_in, const int* in_sizes, int n_in,
                              void* d_out, int out_size) {
    const float* x1 = (const float*)d_in[0];
    const float* x2 = (const float*)d_in[1];
    float* out = (float*)d_out;

    normalize_kernel<<<TWO_N / 16, 256>>>(x1, x2);
    simclr_sym_kernel<<<NPAIRS, 256>>>(out);
}

// round 15
// speedup vs baseline: 1.9957x; 1.1344x over previous
#include <cuda_runtime.h>
#include <cuda_bf16.h>
#include <cstdint>

// ContrastiveLoss (NT-Xent) N=4096 D=512 tau=0.1 — FP8(e4m3) symmetric GEMM.
// Upper-triangular 128x128 tile pairs (2080 of 4096); each exp() feeds row and
// (off-diagonal) column denominators. Positive pairs from the bj==bi+32 band.
// Last CTA (atomic counter) computes the final loss.
//
// R14 ncu: tensor 41%, issue 44%, occ 24% -> latency/overhead-bound, not MMA.
// This round: 3-stage cp.async ring with ONE barrier per K-chunk, and a
// mask-free epilogue fast path for the 1984 tiles with no masked elements.

#define TWO_N 8192
#define NROWS 4096
#define DB16  256       // 512 fp8 = 256 b16 units per row
#define INV_SQRT_TAU 3.16227766016837933f

#define MT 128
#define KC 32           // b16 units per stage (= 64 fp8)
#define SSTR 40         // padded smem row stride (b16 units)
#define NBLK 64
#define NPAIRS 2080     // 64*65/2
#define NSTAGE 3
#define HALF_STAGE (MT * SSTR)              // uint16 elems (A or B)
#define STAGE_ELEMS (2 * HALF_STAGE)        // A+B per stage
#define SMEM_BYTES (NSTAGE * STAGE_ELEMS * 2)

__device__ uint16_t g_zn[(size_t)TWO_N * DB16];   // fp8x2 packed
__device__ float g_denom[TWO_N];
__device__ float g_posv[TWO_N];
__device__ unsigned g_ctr;

// ---------------------------------------------------------------------------
// 2 rows per warp: 8 x 16B loads per lane (MLP=8), shfl-only reductions.
__global__ void normalize_kernel(const float* __restrict__ x1,
                                 const float* __restrict__ x2) {
    const int warp = threadIdx.x >> 5;            // 0..7
    const int lane = threadIdx.x & 31;
    const int row0 = blockIdx.x * 16 + warp * 2;  // 512 blocks
    const int row1 = row0 + 1;

    const float4* s0 = (const float4*)((row0 < NROWS)
                       ? (x1 + (size_t)row0 * 512)
                       : (x2 + (size_t)(row0 - NROWS) * 512));
    const float4* s1 = (const float4*)((row1 < NROWS)
                       ? (x1 + (size_t)row1 * 512)
                       : (x2 + (size_t)(row1 - NROWS) * 512));
    float4 f0[4], f1[4];
    #pragma unroll
    for (int i = 0; i < 4; i++) f0[i] = s0[lane + 32 * i];
    #pragma unroll
    for (int i = 0; i < 4; i++) f1[i] = s1[lane + 32 * i];

    float ss0 = 0.f, ss1 = 0.f;
    #pragma unroll
    for (int i = 0; i < 4; i++) {
        ss0 += f0[i].x * f0[i].x + f0[i].y * f0[i].y + f0[i].z * f0[i].z + f0[i].w * f0[i].w;
        ss1 += f1[i].x * f1[i].x + f1[i].y * f1[i].y + f1[i].z * f1[i].z + f1[i].w * f1[i].w;
    }
    #pragma unroll
    for (int o = 16; o > 0; o >>= 1) {
        ss0 += __shfl_xor_sync(0xffffffffu, ss0, o);
        ss1 += __shfl_xor_sync(0xffffffffu, ss1, o);
    }

    const float sc0 = INV_SQRT_TAU / fmaxf(sqrtf(ss0), 1e-8f);
    const float sc1 = INV_SQRT_TAU / fmaxf(sqrtf(ss1), 1e-8f);
    uint32_t* d0 = (uint32_t*)g_zn + (size_t)row0 * 128;
    uint32_t* d1 = (uint32_t*)g_zn + (size_t)row1 * 128;
    #pragma unroll
    for (int i = 0; i < 4; i++) {
        uint16_t lo, hi;
        asm("cvt.rn.satfinite.e4m3x2.f32 %0, %1, %2;"
            : "=h"(lo) : "f"(f0[i].y * sc0), "f"(f0[i].x * sc0));
        asm("cvt.rn.satfinite.e4m3x2.f32 %0, %1, %2;"
            : "=h"(hi) : "f"(f0[i].w * sc0), "f"(f0[i].z * sc0));
        d0[lane + 32 * i] = (uint32_t)lo | ((uint32_t)hi << 16);
        asm("cvt.rn.satfinite.e4m3x2.f32 %0, %1, %2;"
            : "=h"(lo) : "f"(f1[i].y * sc1), "f"(f1[i].x * sc1));
        asm("cvt.rn.satfinite.e4m3x2.f32 %0, %1, %2;"
            : "=h"(hi) : "f"(f1[i].w * sc1), "f"(f1[i].z * sc1));
        d1[lane + 32 * i] = (uint32_t)lo | ((uint32_t)hi << 16);
    }
    if (lane == 0) {
        g_denom[row0] = 0.f;
        g_denom[row1] = 0.f;
        if (row0 == 0) g_ctr = 0u;
    }
}

// ---------------------------------------------------------------------------
__device__ __forceinline__ void cp_async16(uint32_t saddr, const void* gaddr) {
    asm volatile("cp.async.cg.shared.global [%0], [%1], 16;\n"
                 :: "r"(saddr), "l"(gaddr));
}
__device__ __forceinline__ void cp_commit() {
    asm volatile("cp.async.commit_group;\n" ::: "memory");
}
__device__ __forceinline__ void cp_wait1() {
    asm volatile("cp.async.wait_group 1;\n" ::: "memory");
}
__device__ __forceinline__ void cp_wait0() {
    asm volatile("cp.async.wait_group 0;\n" ::: "memory");
}

extern __shared__ __align__(16) uint16_t smem_ring[];

__global__ __launch_bounds__(256, 2)
void simclr_sym_kernel(float* __restrict__ out) {
    __shared__ float s_rden[MT];
    __shared__ float s_cden[MT];

    // ---- decode linear pair index -> (bi, bj) with bi <= bj ----
    const int idx = blockIdx.x;
    int bi = (int)(64.5f - sqrtf(64.5f * 64.5f - 2.0f * (float)idx));
    if (bi < 0) bi = 0;
    if (bi > NBLK - 1) bi = NBLK - 1;
    while (bi * (129 - bi) / 2 > idx) bi--;
    while ((bi + 1) * (128 - bi) / 2 <= idx) bi++;
    const int bj = bi + (idx - bi * (129 - bi) / 2);
    const int r0 = bi * MT;
    const int c0 = bj * MT;
    const bool offdiag = (bi != bj);
    const bool masked  = (bi == bj) || (bj == bi + 32);   // tiles with masked elems

    const int t    = threadIdx.x;
    const int lane = t & 31;
    const int warp = t >> 5;
    const int m_base = (warp >> 1) * 32;   // 4 warps along M
    const int n_base = (warp & 1) * 64;    // 2 warps along N

    if (t < MT) { s_rden[t] = 0.f; s_cden[t] = 0.f; }

    // ldmatrix per-lane addressing (b16 units)
    const int a_r  = lane & 15;
    const int a_c8 = (lane >> 4) << 3;
    const int b_r  = (lane & 7) + ((lane >> 4) << 3);
    const int b_c8 = ((lane >> 3) & 1) << 3;

    float acc[2][8][4];
    #pragma unroll
    for (int mi = 0; mi < 2; mi++)
        #pragma unroll
        for (int ni = 0; ni < 8; ni++)
            #pragma unroll
            for (int q = 0; q < 4; q++) acc[mi][ni][q] = 0.f;

    // ---- stage loader: fills stage s with K-chunk k0 (A then B) ----
    auto load_stage = [&](int k0, int s) {
        uint16_t* sA = smem_ring + s * STAGE_ELEMS;
        uint16_t* sB = sA + HALF_STAGE;
        #pragma unroll
        for (int rep = 0; rep < 2; rep++) {
            const int i2 = t + rep * 256;
            const int row = i2 >> 2, chk = i2 & 3;
            const uint16_t* ga = g_zn + (size_t)(r0 + row) * DB16 + k0 + chk * 8;
            cp_async16((uint32_t)__cvta_generic_to_shared(&sA[row * SSTR + chk * 8]), ga);
        }
        #pragma unroll
        for (int rep = 0; rep < 2; rep++) {
            const int i2 = t + rep * 256;
            const int row = i2 >> 2, chk = i2 & 3;
            const uint16_t* gb = g_zn + (size_t)(c0 + row) * DB16 + k0 + chk * 8;
            cp_async16((uint32_t)__cvta_generic_to_shared(&sB[row * SSTR + chk * 8]), gb);
        }
    };

    load_stage(0, 0);
    cp_commit();
    load_stage(KC, 1);
    cp_commit();

    const int NKC = DB16 / KC;  // 8
    int stage = 0;
    for (int kc = 0; kc < NKC; kc++) {
        if (kc + 2 < NKC) cp_wait1(); else if (kc + 1 < NKC) cp_wait1(); else cp_wait0();
        __syncthreads();            // stage `stage` ready for ALL warps; stage
                                    // (stage+2)%3 fully consumed (iter kc-1)

        const uint16_t* Ab = smem_ring + stage * STAGE_ELEMS;
        const uint16_t* Bb = Ab + HALF_STAGE;

        #pragma unroll
        for (int ks = 0; ks < KC; ks += 16) {
            uint32_t a[2][4];
            #pragma unroll
            for (int mi = 0; mi < 2; mi++) {
                uint32_t ad = (uint32_t)__cvta_generic_to_shared(
                    Ab + (m_base + mi * 16 + a_r) * SSTR + ks + a_c8);
                asm volatile(
                    "ldmatrix.sync.aligned.m8n8.x4.shared.b16 {%0,%1,%2,%3}, [%4];\n"
                    : "=r"(a[mi][0]), "=r"(a[mi][1]), "=r"(a[mi][2]), "=r"(a[mi][3])
                    : "r"(ad));
            }
            #pragma unroll
            for (int ng = 0; ng < 4; ng++) {
                uint32_t b0, b1, b2, b3;
                uint32_t bd = (uint32_t)__cvta_generic_to_shared(
                    Bb + (n_base + ng * 16 + b_r) * SSTR + ks + b_c8);
                asm volatile(
                    "ldmatrix.sync.aligned.m8n8.x4.shared.b16 {%0,%1,%2,%3}, [%4];\n"
                    : "=r"(b0), "=r"(b1), "=r"(b2), "=r"(b3) : "r"(bd));
                #pragma unroll
                for (int mi = 0; mi < 2; mi++) {
                    asm volatile(
                        "mma.sync.aligned.m16n8k32.row.col.f32.e4m3.e4m3.f32 "
                        "{%0,%1,%2,%3}, {%4,%5,%6,%7}, {%8,%9}, {%0,%1,%2,%3};\n"
                        : "+f"(acc[mi][2 * ng][0]), "+f"(acc[mi][2 * ng][1]),
                          "+f"(acc[mi][2 * ng][2]), "+f"(acc[mi][2 * ng][3])
                        : "r"(a[mi][0]), "r"(a[mi][1]), "r"(a[mi][2]), "r"(a[mi][3]),
                          "r"(b0), "r"(b1));
                    asm volatile(
                        "mma.sync.aligned.m16n8k32.row.col.f32.e4m3.e4m3.f32 "
                        "{%0,%1,%2,%3}, {%4,%5,%6,%7}, {%8,%9}, {%0,%1,%2,%3};\n"
                        : "+f"(acc[mi][2 * ng + 1][0]), "+f"(acc[mi][2 * ng + 1][1]),
                          "+f"(acc[mi][2 * ng + 1][2]), "+f"(acc[mi][2 * ng + 1][3])
                        : "r"(a[mi][0]), "r"(a[mi][1]), "r"(a[mi][2]), "r"(a[mi][3]),
                          "r"(b2), "r"(b3));
                }
            }
        }

        if (kc + 2 < NKC) {
            load_stage((kc + 2) * KC, (stage + 2) % NSTAGE);
            cp_commit();
        }
        stage = (stage + 1) % NSTAGE;
    }

    // ---- epilogue: exp + row sums + (off-diag) col sums ----
    const int g = lane >> 2, tig = lane & 3;
    float cp[8][2];
    #pragma unroll
    for (int ni = 0; ni < 8; ni++) { cp[ni][0] = 0.f; cp[ni][1] = 0.f; }

    #pragma unroll
    for (int mi = 0; mi < 2; mi++) {
        float rs0 = 0.f, rs1 = 0.f;
        const int rA = r0 + m_base + mi * 16 + g;
        const int rB = rA + 8;
        if (!masked) {
            // fast path: no masked elements anywhere in this tile
            #pragma unroll
            for (int ni = 0; ni < 8; ni++) {
                const float e0 = __expf(acc[mi][ni][0]);
                const float e1 = __expf(acc[mi][ni][1]);
                const float e2 = __expf(acc[mi][ni][2]);
                const float e3 = __expf(acc[mi][ni][3]);
                rs0 += e0 + e1;
                rs1 += e2 + e3;
                cp[ni][0] += e0 + e2;
                cp[ni][1] += e1 + e3;
            }
        } else {
            auto proc = [&](int row, int col, float v, float& rs, float& cq) {
                if (((col ^ row) & 4095) == 0) {
                    if (col != row) {           // positive pair: capture, excluded
                        g_posv[row] = v;
                        g_posv[col] = v;
                    }
                } else {
                    const float e = __expf(v);
                    rs += e;
                    cq += e;
                }
            };
            #pragma unroll
            for (int ni = 0; ni < 8; ni++) {
                const int cA = c0 + n_base + ni * 8 + tig * 2;
                proc(rA, cA,     acc[mi][ni][0], rs0, cp[ni][0]);
                proc(rA, cA + 1, acc[mi][ni][1], rs0, cp[ni][1]);
                proc(rB, cA,     acc[mi][ni][2], rs1, cp[ni][0]);
                proc(rB, cA + 1, acc[mi][ni][3], rs1, cp[ni][1]);
            }
        }
        rs0 += __shfl_xor_sync(0xffffffffu, rs0, 1);
        rs0 += __shfl_xor_sync(0xffffffffu, rs0, 2);
        rs1 += __shfl_xor_sync(0xffffffffu, rs1, 1);
        rs1 += __shfl_xor_sync(0xffffffffu, rs1, 2);
        if (tig == 0) {
            atomicAdd(&s_rden[m_base + mi * 16 + g],     rs0);
            atomicAdd(&s_rden[m_base + mi * 16 + g + 8], rs1);
        }
    }

    if (offdiag) {
        // column sums: butterfly over the g bits (lane bits 2..4)
        #pragma unroll
        for (int ni = 0; ni < 8; ni++) {
            #pragma unroll
            for (int qc = 0; qc < 2; qc++) {
                float s = cp[ni][qc];
                s += __shfl_xor_sync(0xffffffffu, s, 4);
                s += __shfl_xor_sync(0xffffffffu, s, 8);
                s += __shfl_xor_sync(0xffffffffu, s, 16);
                if (g == 0)
                    atomicAdd(&s_cden[n_base + ni * 8 + tig * 2 + qc], s);
            }
        }
    }

    __syncthreads();
    if (t < MT) {
        atomicAdd(&g_denom[r0 + t], s_rden[t]);
        if (offdiag) atomicAdd(&g_denom[c0 + t], s_cden[t]);
    }

    // ---- fused final reduction: last CTA computes the loss ----
    __threadfence();
    __shared__ unsigned s_last;
    if (t == 0) s_last = (atomicAdd(&g_ctr, 1u) == NPAIRS - 1) ? 1u : 0u;
    __syncthreads();
    if (s_last) {
        float v = 0.f;
        #pragma unroll
        for (int r = 0; r < 32; r++) {
            const int i = t + r * 256;
            v += g_posv[i] - __logf(g_denom[i]);
        }
        #pragma unroll
        for (int o = 16; o > 0; o >>= 1) v += __shfl_xor_sync(0xffffffffu, v, o);
        __shared__ float sr[8];
        if ((t & 31) == 0) sr[t >> 5] = v;
        __syncthreads();
        if (t == 0) {
            float s = 0.f;
            #pragma unroll
            for (int i = 0; i < 8; i++) s += sr[i];
            out[0] = -s * (1.0f / (float)TWO_N);
        }
    }
}

// ---------------------------------------------------------------------------
extern "C" void kernel_launch(void* const* d_in, const int* in_sizes, int n_in,
                              void* d_out, int out_size) {
    const float* x1 = (const float*)d_in[0];
    const float* x2 = (const float*)d_in[1];
    float* out = (float*)d_out;

    cudaFuncSetAttribute(simclr_sym_kernel,
                         cudaFuncAttributeMaxDynamicSharedMemorySize, SMEM_BYTES);

    normalize_kernel<<<TWO_N / 16, 256>>>(x1, x2);
    simclr_sym_kernel<<<NPAIRS, 256, SMEM_BYTES>>>(out);
}